// round 3
// baseline (speedup 1.0000x reference)
#include <cuda_runtime.h>
#include <math.h>

// ---------------------------------------------------------------------------
// E3GNN, N=512 nodes, fully connected (E=512*511), MULT=NVEC=1, F=MLP=128,
// HDIM=16, NBLOCKS=2, NORM_C=1, readout NV=2, NH=32.
//
//  * First phi_e layer folded into per-node hs/hr precomputes.
//  * One CTA per receiver -> segment sums are CTA-local.
//  * 4 per-edge 128x128 GEMMs with packed fma.rn.f32x2 (full-rate fp32).
// ---------------------------------------------------------------------------

#define NN    512
#define EPN   511
#define FD    128
#define ASTR  68          // smem activation row stride (floats)
#define TILE  64          // edges per tile
#define NTILE 8           // ceil(511/64)

// -------------------- device scratch (no allocs allowed) -------------------
__device__ float g_vec0[NN * 3];
__device__ float g_vec [NN * 3];
__device__ float g_hf  [NN * FD];
__device__ float g_hs  [NN * FD];
__device__ float g_hr  [NN * FD];
__device__ float g_magg[NN * FD];
__device__ float g_vac [NN * 3];

// -------------------- helpers ----------------------------------------------
__device__ __forceinline__ float siluf(float x) { return x / (1.f + __expf(-x)); }
__device__ __forceinline__ float sigmf(float x) { return 1.f / (1.f + __expf(-x)); }

__device__ __forceinline__ unsigned long long pack2(float x) {
    unsigned long long r;
    unsigned u = __float_as_uint(x);
    asm("mov.b64 %0, {%1, %1};" : "=l"(r) : "r"(u));
    return r;
}
__device__ __forceinline__ float2 unpack2(unsigned long long v) {
    unsigned lo, hi;
    asm("mov.b64 {%0, %1}, %2;" : "=r"(lo), "=r"(hi) : "l"(v));
    return make_float2(__uint_as_float(lo), __uint_as_float(hi));
}
#define FMA2(d, a, b) asm("fma.rn.f32x2 %0, %1, %2, %0;" : "+l"(d) : "l"(a), "l"(b))

// -------------------- edge-kernel shared memory -----------------------------
struct __align__(16) ES {
    float buf0[FD * ASTR];
    float buf1[FD * ASTR];
    float dv [TILE * 3];
    float len[TILE];
    float l2 [TILE];
    float pxs[TILE];
    float gate[TILE];
    float winf[FD];
    float wxo [FD];
    float w0  [FD];
    float hrb [FD];
    float bb1 [FD];
    float bb2 [FD];
    float bbx0[FD];
    float bbx1[FD];
    float maggs[2 * FD];
    float rvec[3];
    int   sidx[TILE];
};

// C[e][c] = sum_k A[k][e] * Wg[k][c]  (+bias, opt silu), written transposed
// into Cout[c][e]. 256 threads: ec=tid&15 (4 edges), cc=tid>>4 (8 cols).
template <bool ACT>
__device__ __forceinline__ void gemm_stage(const float* __restrict__ A,
                                           const float* __restrict__ Wg,
                                           const float* __restrict__ bias,
                                           float* __restrict__ Cout, int tid)
{
    const int ec = tid & 15, cc = tid >> 4;
    const float* Ap = A + (ec << 2);
    const float* Wp = Wg + (cc << 3);
    unsigned long long acc[4][4];
#pragma unroll
    for (int i = 0; i < 4; i++)
#pragma unroll
        for (int j = 0; j < 4; j++) acc[i][j] = 0ULL;

#pragma unroll 8
    for (int k = 0; k < FD; k++) {
        float4 av = *reinterpret_cast<const float4*>(Ap + k * ASTR);
        const ulonglong2* wrow = reinterpret_cast<const ulonglong2*>(Wp + k * FD);
        ulonglong2 w01 = __ldg(wrow);
        ulonglong2 w23 = __ldg(wrow + 1);
        unsigned long long b0 = w01.x, b1 = w01.y, b2 = w23.x, b3 = w23.y;
        unsigned long long a0 = pack2(av.x), a1 = pack2(av.y),
                           a2 = pack2(av.z), a3 = pack2(av.w);
        FMA2(acc[0][0], a0, b0); FMA2(acc[0][1], a0, b1);
        FMA2(acc[0][2], a0, b2); FMA2(acc[0][3], a0, b3);
        FMA2(acc[1][0], a1, b0); FMA2(acc[1][1], a1, b1);
        FMA2(acc[1][2], a1, b2); FMA2(acc[1][3], a1, b3);
        FMA2(acc[2][0], a2, b0); FMA2(acc[2][1], a2, b1);
        FMA2(acc[2][2], a2, b2); FMA2(acc[2][3], a2, b3);
        FMA2(acc[3][0], a3, b0); FMA2(acc[3][1], a3, b1);
        FMA2(acc[3][2], a3, b2); FMA2(acc[3][3], a3, b3);
    }
#pragma unroll
    for (int i = 0; i < 4; i++) {
        int e = (ec << 2) + i;
#pragma unroll
        for (int j = 0; j < 4; j++) {
            float2 v = unpack2(acc[i][j]);
            int c = (cc << 3) + (j << 1);
            float r0 = v.x + bias[c];
            float r1 = v.y + bias[c + 1];
            if (ACT) { r0 = siluf(r0); r1 = siluf(r1); }
            Cout[c * ASTR + e]       = r0;
            Cout[(c + 1) * ASTR + e] = r1;
        }
    }
}

// -------------------- edge kernel: one CTA per receiver ---------------------
__global__ void __launch_bounds__(256, 2)
kedge(const int* __restrict__ senders,
      const float* __restrict__ We0r0,
      const float* __restrict__ We1, const float* __restrict__ be1,
      const float* __restrict__ We2, const float* __restrict__ be2,
      const float* __restrict__ Winf, const float* __restrict__ binfp,
      const float* __restrict__ Wx0, const float* __restrict__ bx0,
      const float* __restrict__ Wx1, const float* __restrict__ bx1,
      const float* __restrict__ Wxo, const float* __restrict__ bxop)
{
    extern __shared__ char smraw[];
    ES* S = reinterpret_cast<ES*>(smraw);
    const int t = threadIdx.x;
    const int i = blockIdx.x;

    if (t < FD) {
        S->winf[t] = Winf[t];
        S->wxo[t]  = Wxo[t];
        S->w0[t]   = We0r0[t];
        S->hrb[t]  = g_hr[i * FD + t];
        S->bb1[t]  = be1[t];
        S->bb2[t]  = be2[t];
        S->bbx0[t] = bx0[t];
        S->bbx1[t] = bx1[t];
    }
    if (t < 3) S->rvec[t] = g_vec[i * 3 + t];
    const float binf_s = binfp[0];
    const float bxo_s  = bxop[0];

    const int kk = t & 127;        // feature index for act0 / magg phases
    const int hh = t >> 7;         // 0/1 edge-half
    float mreg = 0.f;              // magg partial for (hh, kk)
    float vacc = 0.f;              // vac partial for threads 0..2

    __syncthreads();

    for (int tile = 0; tile < NTILE; tile++) {
        // ---- stage 1: senders, dv, len, l2 -----------------------------
        if (t < TILE) {
            int je = tile * TILE + t;
            bool valid = je < EPN;
            int s = valid ? senders[i * EPN + je] : i;
            S->sidx[t] = s;
            float d0 = 0.f, d1 = 0.f, d2 = 0.f;
            if (valid) {
                d0 = S->rvec[0] - g_vec[s * 3 + 0];
                d1 = S->rvec[1] - g_vec[s * 3 + 1];
                d2 = S->rvec[2] - g_vec[s * 3 + 2];
            }
            S->dv[t * 3 + 0] = d0;
            S->dv[t * 3 + 1] = d1;
            S->dv[t * 3 + 2] = d2;
            float dot = d0 * d0 + d1 * d1 + d2 * d2 + 1e-20f;
            S->l2[t]  = valid ? dot : 0.f;
            S->len[t] = sqrtf(dot);
        }
        __syncthreads();

        // ---- stage 2: act0[k][e] = silu(l2*w0[k] + hs[s][k] + hr[i][k]) -
        {
            float w0v = S->w0[kk];
            float hrv = S->hrb[kk];
#pragma unroll 4
            for (int e = hh; e < TILE; e += 2) {
                int s = S->sidx[e];
                float v = S->l2[e] * w0v + g_hs[s * FD + kk] + hrv;
                S->buf0[kk * ASTR + e] = siluf(v);
            }
        }
        __syncthreads();

        // ---- GEMM1: buf1 = silu(buf0 @ We1 + be1) ----------------------
        gemm_stage<true>(S->buf0, We1, S->bb1, S->buf1, t);
        __syncthreads();

        // ---- GEMM2: buf0 = buf1 @ We2 + be2   (m) ----------------------
        gemm_stage<false>(S->buf1, We2, S->bb2, S->buf0, t);
        __syncthreads();

        // ---- gate[e] = sigmoid(m . winf + binf) ------------------------
        if (t < TILE) {
            float acc = binf_s;
#pragma unroll 8
            for (int k = 0; k < FD; k++) acc += S->buf0[k * ASTR + t] * S->winf[k];
            bool valid = (tile * TILE + t) < EPN;
            S->gate[t] = valid ? sigmf(acc) : 0.f;
        }
        __syncthreads();

        // ---- magg partial + GEMM3: buf1 = silu(buf0 @ Wx0 + bx0) -------
        {
            float part = 0.f;
#pragma unroll 8
            for (int e = hh; e < TILE; e += 2)
                part += S->buf0[kk * ASTR + e] * S->gate[e];
            mreg += part;
        }
        gemm_stage<true>(S->buf0, Wx0, S->bbx0, S->buf1, t);
        __syncthreads();

        // ---- GEMM4: buf0 = silu(buf1 @ Wx1 + bx1) ----------------------
        gemm_stage<true>(S->buf1, Wx1, S->bbx1, S->buf0, t);
        __syncthreads();

        // ---- px[e] = B1 . wxo + bxo; pxs = px/(1+len) ------------------
        if (t < TILE) {
            float acc = bxo_s;
#pragma unroll 8
            for (int k = 0; k < FD; k++) acc += S->buf0[k * ASTR + t] * S->wxo[k];
            S->pxs[t] = acc / (1.f + S->len[t]);
        }
        __syncthreads();

        // ---- vac partial -----------------------------------------------
        if (t < 3) {
            float part = 0.f;
#pragma unroll 8
            for (int e = 0; e < TILE; e++) part += S->pxs[e] * S->dv[e * 3 + t];
            vacc += part;
        }
        __syncthreads();
    }

    // ---- writeout -------------------------------------------------------
    S->maggs[t] = mreg;
    __syncthreads();
    if (t < FD)
        g_magg[i * FD + t] = (S->maggs[t] + S->maggs[FD + t]) * rsqrtf(511.f);
    if (t < 3)
        g_vac[i * 3 + t] = vacc * (1.f / 511.f);
}

// -------------------- setup: center coordinates -----------------------------
__global__ void ksetup(const float* __restrict__ x)
{
    __shared__ float r0[256], r1[256], r2[256];
    __shared__ float mean[3];
    int t = threadIdx.x;
    float s0 = 0.f, s1 = 0.f, s2 = 0.f;
    for (int n = t; n < NN; n += 256) {
        s0 += x[n * 3 + 0]; s1 += x[n * 3 + 1]; s2 += x[n * 3 + 2];
    }
    r0[t] = s0; r1[t] = s1; r2[t] = s2;
    __syncthreads();
    for (int s = 128; s > 0; s >>= 1) {
        if (t < s) { r0[t] += r0[t + s]; r1[t] += r1[t + s]; r2[t] += r2[t + s]; }
        __syncthreads();
    }
    if (t == 0) {
        mean[0] = r0[0] * (1.f / NN);
        mean[1] = r1[0] * (1.f / NN);
        mean[2] = r2[0] * (1.f / NN);
    }
    __syncthreads();
    for (int n = t; n < NN; n += 256) {
#pragma unroll
        for (int c = 0; c < 3; c++) {
            float v = x[n * 3 + c] - mean[c];
            g_vec[n * 3 + c]  = v;
            g_vec0[n * 3 + c] = v;
        }
    }
}

// -------------------- node init: hf, hs, hr (block 0) -----------------------
__global__ void knode0(const float* __restrict__ h,
                       const float* __restrict__ Wh0, const float* __restrict__ bh0,
                       const float* __restrict__ We0, const float* __restrict__ be0)
{
    __shared__ float hrow[16];
    __shared__ float hfs[FD];
    int i = blockIdx.x, c = threadIdx.x;
    if (c < 16) hrow[c] = h[i * 16 + c];
    __syncthreads();
    float acc = bh0[c];
#pragma unroll
    for (int k = 0; k < 16; k++) acc += hrow[k] * Wh0[k * FD + c];
    g_hf[i * FD + c] = acc;
    hfs[c] = acc;
    __syncthreads();
    float s1 = 0.f, s2 = be0[c];
#pragma unroll 8
    for (int k = 0; k < FD; k++) {
        float hv = hfs[k];
        s1 += hv * We0[(1 + k) * FD + c];
        s2 += hv * We0[(129 + k) * FD + c];
    }
    g_hs[i * FD + c] = s1;
    g_hr[i * FD + c] = s2;
}

// -------------------- node update (phi_h) + next-block hs/hr ----------------
__global__ void knode(const float* __restrict__ Wp0, const float* __restrict__ bp0,
                      const float* __restrict__ Wp1, const float* __restrict__ bp1,
                      const float* __restrict__ Wpl, const float* __restrict__ bpl,
                      const float* __restrict__ We0n, const float* __restrict__ be0n,
                      int doNext)
{
    __shared__ float in0[2 * FD];
    __shared__ float t0s[FD];
    __shared__ float t1s[FD];
    int i = blockIdx.x, c = threadIdx.x;

    if (c < 3) g_vec[i * 3 + c] += g_vac[i * 3 + c];

    in0[c] = g_magg[i * FD + c];
    float hf = g_hf[i * FD + c];
    in0[FD + c] = hf;
    __syncthreads();

    float a = bp0[c];
#pragma unroll 8
    for (int k = 0; k < 2 * FD; k++) a += in0[k] * Wp0[k * FD + c];
    t0s[c] = siluf(a);
    __syncthreads();

    float b = bp1[c];
#pragma unroll 8
    for (int k = 0; k < FD; k++) b += t0s[k] * Wp1[k * FD + c];
    t1s[c] = b;
    __syncthreads();

    float d = bpl[c];
#pragma unroll 8
    for (int k = 0; k < FD; k++) d += t1s[k] * Wpl[k * FD + c];
    float nhf = hf + d;
    g_hf[i * FD + c] = nhf;

    if (doNext) {
        t0s[c] = nhf;
        __syncthreads();
        float s1 = 0.f, s2 = be0n[c];
#pragma unroll 8
        for (int k = 0; k < FD; k++) {
            float hv = t0s[k];
            s1 += hv * We0n[(1 + k) * FD + c];
            s2 += hv * We0n[(129 + k) * FD + c];
        }
        g_hs[i * FD + c] = s1;
        g_hr[i * FD + c] = s2;
    }
}

// -------------------- readout -----------------------------------------------
__global__ void kout(const float* __restrict__ Wv,
                     const float* __restrict__ Wr, const float* __restrict__ br,
                     float* __restrict__ out)
{
    __shared__ float red[FD];
    __shared__ float p[FD];
    int i = blockIdx.x, c = threadIdx.x;
    float hf = g_hf[i * FD + c];

    red[c] = hf;
    __syncthreads();
    for (int s = 64; s > 0; s >>= 1) {
        if (c < s) red[c] = fmaxf(red[c], red[c + s]);
        __syncthreads();
    }
    float mx = red[0];
    __syncthreads();
    float ex = __expf(hf - mx);
    red[c] = ex;
    __syncthreads();
    for (int s = 64; s > 0; s >>= 1) {
        if (c < s) red[c] += red[c + s];
        __syncthreads();
    }
    float inv = 1.f / red[0];
    __syncthreads();
    p[c] = ex * inv;
    __syncthreads();

    if (c < 32) {
        float a = br[c];
#pragma unroll 8
        for (int k = 0; k < FD; k++) a += p[k] * Wr[k * 32 + c];
        out[NN * 6 + i * 32 + c] = a;
    }
    if (c < 6) {
        int o = c / 3, cc = c % 3;
        out[i * 6 + c] = (g_vec[i * 3 + cc] - g_vec0[i * 3 + cc]) * Wv[o];
    }
}

// -------------------- host launch -------------------------------------------
extern "C" void kernel_launch(void* const* d_in, const int* in_sizes, int n_in,
                              void* d_out, int out_size)
{
    const float* x   = (const float*)d_in[0];
    const float* h   = (const float*)d_in[1];
    const int* snd   = (const int*)  d_in[2];
    const float* Wh0 = (const float*)d_in[4];
    const float* bh0 = (const float*)d_in[5];
    const float* We0 = (const float*)d_in[6];
    const float* be0 = (const float*)d_in[7];
    const float* We1 = (const float*)d_in[8];
    const float* be1 = (const float*)d_in[9];
    const float* We2 = (const float*)d_in[10];
    const float* be2 = (const float*)d_in[11];
    const float* Winf= (const float*)d_in[12];
    const float* binf= (const float*)d_in[13];
    const float* Wx0 = (const float*)d_in[14];
    const float* bx0 = (const float*)d_in[15];
    const float* Wx1 = (const float*)d_in[16];
    const float* bx1 = (const float*)d_in[17];
    const float* Wxo = (const float*)d_in[18];
    const float* bxo = (const float*)d_in[19];
    const float* Wp0 = (const float*)d_in[20];
    const float* bp0 = (const float*)d_in[21];
    const float* Wp1 = (const float*)d_in[22];
    const float* bp1 = (const float*)d_in[23];
    const float* Wpl = (const float*)d_in[24];
    const float* bpl = (const float*)d_in[25];
    const float* Wv  = (const float*)d_in[26];
    const float* Wr  = (const float*)d_in[27];
    const float* br  = (const float*)d_in[28];
    float* out = (float*)d_out;

    int smem = (int)sizeof(ES);
    cudaFuncSetAttribute(kedge, cudaFuncAttributeMaxDynamicSharedMemorySize, smem);

    const int WB  = FD * FD;     // 128*128 per-block weight stride
    const int W0B = 257 * FD;    // We0 per-block stride
    const int WP0 = 2 * FD * FD; // Wp0 per-block stride

    ksetup<<<1, 256>>>(x);
    knode0<<<NN, FD>>>(h, Wh0, bh0, We0, be0);

    for (int b = 0; b < 2; b++) {
        kedge<<<NN, 256, smem>>>(snd,
            We0 + b * W0B,
            We1 + b * WB, be1 + b * FD,
            We2 + b * WB, be2 + b * FD,
            Winf + b * FD, binf + b,
            Wx0 + b * WB, bx0 + b * FD,
            Wx1 + b * WB, bx1 + b * FD,
            Wxo + b * FD, bxo + b);
        knode<<<NN, FD>>>(Wp0 + b * WP0, bp0 + b * FD,
                          Wp1 + b * WB,  bp1 + b * FD,
                          Wpl + b * WB,  bpl + b * FD,
                          We0 + W0B, be0 + FD, b == 0 ? 1 : 0);
    }

    kout<<<NN, FD>>>(Wv, Wr, br, out);
}

// round 4
// speedup vs baseline: 1.2504x; 1.2504x over previous
#include <cuda_runtime.h>
#include <math.h>

// ---------------------------------------------------------------------------
// E3GNN, N=512 nodes, fully connected (E=512*511), F=MLP=128, NBLOCKS=2.
//  * First phi_e layer folded into per-node hs/hr precomputes.
//  * One CTA per receiver; segment sums CTA-local.
//  * 4 per-edge 128x128 GEMMs: packed fma.rn.f32x2, weights staged through
//    smem in double-buffered 16-row chunks (kills L1 thrash / L2 latency).
// ---------------------------------------------------------------------------

#define NN    512
#define EPN   511
#define FD    128
#define ASTR  68          // smem activation row stride (floats)
#define TILE  64          // edges per tile
#define NTILE 8           // ceil(511/64)
#define CH    16          // weight chunk rows
#define NCH   8           // chunks per 128x128 GEMM
#define CHF   (CH * FD)   // floats per chunk (2048)

// -------------------- device scratch (no allocs allowed) -------------------
__device__ float g_vec0[NN * 3];
__device__ float g_vec [NN * 3];
__device__ float g_hf  [NN * FD];
__device__ float g_hs  [NN * FD];
__device__ float g_hr  [NN * FD];
__device__ float g_magg[NN * FD];
__device__ float g_vac [NN * 3];
__device__ float g_dummy[32];

// -------------------- helpers ----------------------------------------------
__device__ __forceinline__ float siluf(float x) { return x / (1.f + __expf(-x)); }
__device__ __forceinline__ float sigmf(float x) { return 1.f / (1.f + __expf(-x)); }

__device__ __forceinline__ unsigned long long pack2(float x) {
    unsigned long long r;
    unsigned u = __float_as_uint(x);
    asm("mov.b64 %0, {%1, %1};" : "=l"(r) : "r"(u));
    return r;
}
__device__ __forceinline__ float2 unpack2(unsigned long long v) {
    unsigned lo, hi;
    asm("mov.b64 {%0, %1}, %2;" : "=r"(lo), "=r"(hi) : "l"(v));
    return make_float2(__uint_as_float(lo), __uint_as_float(hi));
}
#define FMA2(d, a, b) asm("fma.rn.f32x2 %0, %1, %2, %0;" : "+l"(d) : "l"(a), "l"(b))

// -------------------- edge-kernel shared memory -----------------------------
struct __align__(16) ES {
    float Wbuf[2 * CHF];      // double-buffered weight chunk (16 KB)
    float buf0[FD * ASTR];
    float buf1[FD * ASTR];
    float dv [TILE * 3];
    float len[TILE];
    float l2 [TILE];
    float pxs[TILE];
    float gate[TILE];
    float winf[FD];
    float wxo [FD];
    float w0  [FD];
    float hrb [FD];
    float bb1 [FD];
    float bb2 [FD];
    float bbx0[FD];
    float bbx1[FD];
    float maggs[2 * FD];
    float vred[192];
    float vaccs[4];
    float rvec[3];
    int   sidx[TILE];
};

// C[e][c] = sum_k A[k][e] * Wg[k][c]  (+bias, opt silu), written transposed
// into Cout[c][e]. Weights flow global -> regs -> smem chunk, double-buffered.
// During the last chunk, chunk 0 of Wnext is staged (cross-GEMM pipeline).
// Ends with a __syncthreads that publishes both Cout and the staged Wnext.
template <bool ACT>
__device__ __forceinline__ void gemm_stage(const float* __restrict__ A,
                                           const float* __restrict__ Wg,
                                           const float* __restrict__ Wnext,
                                           const float* __restrict__ bias,
                                           float* __restrict__ Cout,
                                           float* __restrict__ Wbuf, int tid)
{
    const int ec = tid & 15, cc = tid >> 4;
    const float* Ap = A + (ec << 2);
    unsigned long long acc[4][4];
#pragma unroll
    for (int i = 0; i < 4; i++)
#pragma unroll
        for (int j = 0; j < 4; j++) acc[i][j] = 0ULL;

    for (int ch = 0; ch < NCH; ch++) {
        // prefetch next chunk (or next GEMM's chunk 0) into registers
        const float* src = (ch < NCH - 1) ? (Wg + (ch + 1) * CHF) : Wnext;
        float4 p0 = __ldg(reinterpret_cast<const float4*>(src) + tid);
        float4 p1 = __ldg(reinterpret_cast<const float4*>(src + CHF / 2) + tid);

        // compute on current chunk
        const float* Wb = Wbuf + (ch & 1) * CHF + (cc << 3);
        const float* Ac = Ap + (ch * CH) * ASTR;
#pragma unroll
        for (int kl = 0; kl < CH; kl++) {
            float4 av = *reinterpret_cast<const float4*>(Ac + kl * ASTR);
            const ulonglong2* wrow = reinterpret_cast<const ulonglong2*>(Wb + kl * FD);
            ulonglong2 w01 = wrow[0];
            ulonglong2 w23 = wrow[1];
            unsigned long long b0 = w01.x, b1 = w01.y, b2 = w23.x, b3 = w23.y;
            unsigned long long a0 = pack2(av.x), a1 = pack2(av.y),
                               a2 = pack2(av.z), a3 = pack2(av.w);
            FMA2(acc[0][0], a0, b0); FMA2(acc[0][1], a0, b1);
            FMA2(acc[0][2], a0, b2); FMA2(acc[0][3], a0, b3);
            FMA2(acc[1][0], a1, b0); FMA2(acc[1][1], a1, b1);
            FMA2(acc[1][2], a1, b2); FMA2(acc[1][3], a1, b3);
            FMA2(acc[2][0], a2, b0); FMA2(acc[2][1], a2, b1);
            FMA2(acc[2][2], a2, b2); FMA2(acc[2][3], a2, b3);
            FMA2(acc[3][0], a3, b0); FMA2(acc[3][1], a3, b1);
            FMA2(acc[3][2], a3, b2); FMA2(acc[3][3], a3, b3);
        }

        // publish prefetched chunk into the other buffer
        float* dst = Wbuf + ((ch + 1) & 1) * CHF;
        reinterpret_cast<float4*>(dst)[tid]            = p0;
        reinterpret_cast<float4*>(dst + CHF / 2)[tid]  = p1;
        if (ch < NCH - 1) __syncthreads();
    }

    // epilogue: bias (+silu), transposed store
#pragma unroll
    for (int i = 0; i < 4; i++) {
        int e = (ec << 2) + i;
#pragma unroll
        for (int j = 0; j < 4; j++) {
            float2 v = unpack2(acc[i][j]);
            int c = (cc << 3) + (j << 1);
            float r0 = v.x + bias[c];
            float r1 = v.y + bias[c + 1];
            if (ACT) { r0 = siluf(r0); r1 = siluf(r1); }
            Cout[c * ASTR + e]       = r0;
            Cout[(c + 1) * ASTR + e] = r1;
        }
    }
    __syncthreads();
}

// -------------------- edge kernel: one CTA per receiver ---------------------
__global__ void __launch_bounds__(256, 2)
kedge(const int* __restrict__ senders,
      const float* __restrict__ We0r0,
      const float* __restrict__ We1, const float* __restrict__ be1,
      const float* __restrict__ We2, const float* __restrict__ be2,
      const float* __restrict__ Winf, const float* __restrict__ binfp,
      const float* __restrict__ Wx0, const float* __restrict__ bx0,
      const float* __restrict__ Wx1, const float* __restrict__ bx1,
      const float* __restrict__ Wxo, const float* __restrict__ bxop)
{
    extern __shared__ char smraw[];
    ES* S = reinterpret_cast<ES*>(smraw);
    const int t = threadIdx.x;
    const int i = blockIdx.x;

    if (t < FD) {
        S->winf[t] = Winf[t];
        S->wxo[t]  = Wxo[t];
        S->w0[t]   = We0r0[t];
        S->hrb[t]  = g_hr[i * FD + t];
        S->bb1[t]  = be1[t];
        S->bb2[t]  = be2[t];
        S->bbx0[t] = bx0[t];
        S->bbx1[t] = bx1[t];
    }
    if (t < 3) { S->rvec[t] = g_vec[i * 3 + t]; S->vaccs[t] = 0.f; }
    const float binf_s = binfp[0];
    const float bxo_s  = bxop[0];

    // prologue: stage We1 chunk 0 into Wbuf[0]
    {
        float4 p0 = __ldg(reinterpret_cast<const float4*>(We1) + t);
        float4 p1 = __ldg(reinterpret_cast<const float4*>(We1 + CHF / 2) + t);
        reinterpret_cast<float4*>(S->Wbuf)[t]           = p0;
        reinterpret_cast<float4*>(S->Wbuf + CHF / 2)[t] = p1;
    }

    const int kk = t & 127;        // feature index
    const int hh = t >> 7;         // edge half
    float mreg = 0.f;              // magg partial for (hh, kk)

    __syncthreads();

    for (int tile = 0; tile < NTILE; tile++) {
        // ---- stage 1: senders, dv, len, l2 -----------------------------
        if (t < TILE) {
            int je = tile * TILE + t;
            bool valid = je < EPN;
            int s = valid ? senders[i * EPN + je] : i;
            S->sidx[t] = s;
            float d0 = 0.f, d1 = 0.f, d2 = 0.f;
            if (valid) {
                d0 = S->rvec[0] - g_vec[s * 3 + 0];
                d1 = S->rvec[1] - g_vec[s * 3 + 1];
                d2 = S->rvec[2] - g_vec[s * 3 + 2];
            }
            S->dv[t * 3 + 0] = d0;
            S->dv[t * 3 + 1] = d1;
            S->dv[t * 3 + 2] = d2;
            float dot = d0 * d0 + d1 * d1 + d2 * d2 + 1e-20f;
            S->l2[t]  = valid ? dot : 0.f;
            S->len[t] = sqrtf(dot);
        }
        __syncthreads();

        // ---- stage 2: act0[k][e] = silu(l2*w0[k] + hs[s][k] + hr[i][k]) -
        {
            float w0v = S->w0[kk];
            float hrv = S->hrb[kk];
#pragma unroll 4
            for (int e = hh; e < TILE; e += 2) {
                int s = S->sidx[e];
                float v = S->l2[e] * w0v + g_hs[s * FD + kk] + hrv;
                S->buf0[kk * ASTR + e] = siluf(v);
            }
        }
        __syncthreads();

        // ---- GEMM1: buf1 = silu(buf0 @ We1 + be1) ----------------------
        gemm_stage<true >(S->buf0, We1, We2, S->bb1, S->buf1, S->Wbuf, t);
        // ---- GEMM2: buf0 = buf1 @ We2 + be2   (m) ----------------------
        gemm_stage<false>(S->buf1, We2, Wx0, S->bb2, S->buf0, S->Wbuf, t);

        // ---- gate[e] = sigmoid(m . winf + binf) ------------------------
        if (t < TILE) {
            float a0 = 0.f, a1 = 0.f, a2 = 0.f, a3 = 0.f;
#pragma unroll 8
            for (int k = 0; k < FD; k += 4) {
                a0 += S->buf0[(k    ) * ASTR + t] * S->winf[k];
                a1 += S->buf0[(k + 1) * ASTR + t] * S->winf[k + 1];
                a2 += S->buf0[(k + 2) * ASTR + t] * S->winf[k + 2];
                a3 += S->buf0[(k + 3) * ASTR + t] * S->winf[k + 3];
            }
            bool valid = (tile * TILE + t) < EPN;
            S->gate[t] = valid ? sigmf(binf_s + ((a0 + a1) + (a2 + a3))) : 0.f;
        }
        __syncthreads();

        // ---- magg partial ----------------------------------------------
        {
            const float* row = S->buf0 + kk * ASTR + hh * 32;
            const float* gt  = S->gate + hh * 32;
            float p0 = 0.f, p1 = 0.f;
#pragma unroll
            for (int e = 0; e < 32; e += 4) {
                float4 r = *reinterpret_cast<const float4*>(row + e);
                float4 g = *reinterpret_cast<const float4*>(gt + e);
                p0 += r.x * g.x + r.y * g.y;
                p1 += r.z * g.z + r.w * g.w;
            }
            mreg += p0 + p1;
        }

        // ---- GEMM3: buf1 = silu(buf0 @ Wx0 + bx0) ----------------------
        gemm_stage<true>(S->buf0, Wx0, Wx1, S->bbx0, S->buf1, S->Wbuf, t);
        // ---- GEMM4: buf0 = silu(buf1 @ Wx1 + bx1) ----------------------
        gemm_stage<true>(S->buf1, Wx1, We1, S->bbx1, S->buf0, S->Wbuf, t);

        // ---- px[e] = B1 . wxo + bxo; pxs = px/(1+len) ------------------
        if (t < TILE) {
            float a0 = 0.f, a1 = 0.f, a2 = 0.f, a3 = 0.f;
#pragma unroll 8
            for (int k = 0; k < FD; k += 4) {
                a0 += S->buf0[(k    ) * ASTR + t] * S->wxo[k];
                a1 += S->buf0[(k + 1) * ASTR + t] * S->wxo[k + 1];
                a2 += S->buf0[(k + 2) * ASTR + t] * S->wxo[k + 2];
                a3 += S->buf0[(k + 3) * ASTR + t] * S->wxo[k + 3];
            }
            S->pxs[t] = (bxo_s + ((a0 + a1) + (a2 + a3))) / (1.f + S->len[t]);
        }
        __syncthreads();

        // ---- vac partial (warp-parallel) -------------------------------
        if (t < 192) {
            int e = t & 63, c = t >> 6;
            S->vred[c * 64 + e] = S->pxs[e] * S->dv[e * 3 + c];
        }
        __syncthreads();
        if (t < 96) {
            int c = t >> 5, l = t & 31;
            float v = S->vred[c * 64 + l] + S->vred[c * 64 + 32 + l];
#pragma unroll
            for (int o = 16; o; o >>= 1) v += __shfl_down_sync(0xffffffffu, v, o);
            if (l == 0) S->vaccs[c] += v;
        }
        __syncthreads();
    }

    // ---- writeout -------------------------------------------------------
    S->maggs[t] = mreg;
    __syncthreads();
    if (t < FD)
        g_magg[i * FD + t] = (S->maggs[t] + S->maggs[FD + t]) * rsqrtf(511.f);
    if (t < 3)
        g_vac[i * 3 + t] = S->vaccs[t] * (1.f / 511.f);
}

// -------------------- setup: center coordinates -----------------------------
__global__ void ksetup(const float* __restrict__ x)
{
    __shared__ float r0[256], r1[256], r2[256];
    __shared__ float mean[3];
    int t = threadIdx.x;
    float s0 = 0.f, s1 = 0.f, s2 = 0.f;
    for (int n = t; n < NN; n += 256) {
        s0 += x[n * 3 + 0]; s1 += x[n * 3 + 1]; s2 += x[n * 3 + 2];
    }
    r0[t] = s0; r1[t] = s1; r2[t] = s2;
    __syncthreads();
    for (int s = 128; s > 0; s >>= 1) {
        if (t < s) { r0[t] += r0[t + s]; r1[t] += r1[t + s]; r2[t] += r2[t + s]; }
        __syncthreads();
    }
    if (t == 0) {
        mean[0] = r0[0] * (1.f / NN);
        mean[1] = r1[0] * (1.f / NN);
        mean[2] = r2[0] * (1.f / NN);
    }
    __syncthreads();
    for (int n = t; n < NN; n += 256) {
#pragma unroll
        for (int c = 0; c < 3; c++) {
            float v = x[n * 3 + c] - mean[c];
            g_vec[n * 3 + c]  = v;
            g_vec0[n * 3 + c] = v;
        }
    }
}

// -------------------- dummy (shifts ncu -s 5 capture onto kedge) ------------
__global__ void kdummy() { g_dummy[threadIdx.x] = 0.f; }

// -------------------- node init: hf, hs, hr (block 0) -----------------------
__global__ void __launch_bounds__(256) knode0(
    const float* __restrict__ h,
    const float* __restrict__ Wh0, const float* __restrict__ bh0,
    const float* __restrict__ We0, const float* __restrict__ be0)
{
    __shared__ float hrow[16];
    __shared__ float hfs[FD];
    __shared__ float part[256];
    int i = blockIdx.x, t = threadIdx.x;
    int c = t & 127, hh = t >> 7;
    if (t < 16) hrow[t] = h[i * 16 + t];
    __syncthreads();
    if (t < FD) {
        float acc = bh0[t];
#pragma unroll
        for (int k = 0; k < 16; k++) acc += hrow[k] * Wh0[k * FD + t];
        g_hf[i * FD + t] = acc;
        hfs[t] = acc;
    }
    __syncthreads();
    {
        float a0 = 0.f, a1 = 0.f, b0 = 0.f, b1 = 0.f;
        const float* W1 = We0 + (1 + hh * 64) * FD;
        const float* W2 = We0 + (129 + hh * 64) * FD;
        const float* xv = hfs + hh * 64;
#pragma unroll 4
        for (int k = 0; k < 64; k += 2) {
            a0 += xv[k] * W1[k * FD + c];       a1 += xv[k + 1] * W1[(k + 1) * FD + c];
            b0 += xv[k] * W2[k * FD + c];       b1 += xv[k + 1] * W2[(k + 1) * FD + c];
        }
        part[t] = a0 + a1;
        __syncthreads();
        if (t < FD) g_hs[i * FD + t] = part[t] + part[t + FD];
        __syncthreads();
        part[t] = b0 + b1;
        __syncthreads();
        if (t < FD) g_hr[i * FD + t] = part[t] + part[t + FD] + be0[t];
    }
}

// -------------------- node update (phi_h) + next-block hs/hr ----------------
__global__ void __launch_bounds__(256) knode(
    const float* __restrict__ Wp0, const float* __restrict__ bp0,
    const float* __restrict__ Wp1, const float* __restrict__ bp1,
    const float* __restrict__ Wpl, const float* __restrict__ bpl,
    const float* __restrict__ We0n, const float* __restrict__ be0n,
    int doNext)
{
    __shared__ float in0[2 * FD];
    __shared__ float t0s[FD];
    __shared__ float t1s[FD];
    __shared__ float nhfs[FD];
    __shared__ float part[256];
    int i = blockIdx.x, t = threadIdx.x;
    int c = t & 127, hh = t >> 7;

    if (t < 3) g_vec[i * 3 + t] += g_vac[i * 3 + t];
    if (t < FD) in0[t] = g_magg[i * FD + t];
    else        in0[t] = g_hf[i * FD + (t - FD)];
    __syncthreads();

    // Wp0: 256 x 128, split k over two halves
    {
        float a0 = 0.f, a1 = 0.f, a2 = 0.f, a3 = 0.f;
        const float* W  = Wp0 + hh * FD * FD;
        const float* xv = in0 + hh * FD;
#pragma unroll 4
        for (int k = 0; k < FD; k += 4) {
            a0 += xv[k]     * W[(k    ) * FD + c];
            a1 += xv[k + 1] * W[(k + 1) * FD + c];
            a2 += xv[k + 2] * W[(k + 2) * FD + c];
            a3 += xv[k + 3] * W[(k + 3) * FD + c];
        }
        part[t] = (a0 + a1) + (a2 + a3);
    }
    __syncthreads();
    if (t < FD) t0s[t] = siluf(part[t] + part[t + FD] + bp0[t]);
    __syncthreads();

    // Wp1: 128 x 128
    {
        float a0 = 0.f, a1 = 0.f, a2 = 0.f, a3 = 0.f;
        const float* W  = Wp1 + hh * 64 * FD;
        const float* xv = t0s + hh * 64;
#pragma unroll 4
        for (int k = 0; k < 64; k += 4) {
            a0 += xv[k]     * W[(k    ) * FD + c];
            a1 += xv[k + 1] * W[(k + 1) * FD + c];
            a2 += xv[k + 2] * W[(k + 2) * FD + c];
            a3 += xv[k + 3] * W[(k + 3) * FD + c];
        }
        part[t] = (a0 + a1) + (a2 + a3);
    }
    __syncthreads();
    if (t < FD) t1s[t] = part[t] + part[t + FD] + bp1[t];
    __syncthreads();

    // Wpl: 128 x 128
    {
        float a0 = 0.f, a1 = 0.f, a2 = 0.f, a3 = 0.f;
        const float* W  = Wpl + hh * 64 * FD;
        const float* xv = t1s + hh * 64;
#pragma unroll 4
        for (int k = 0; k < 64; k += 4) {
            a0 += xv[k]     * W[(k    ) * FD + c];
            a1 += xv[k + 1] * W[(k + 1) * FD + c];
            a2 += xv[k + 2] * W[(k + 2) * FD + c];
            a3 += xv[k + 3] * W[(k + 3) * FD + c];
        }
        part[t] = (a0 + a1) + (a2 + a3);
    }
    __syncthreads();
    if (t < FD) {
        float nhf = g_hf[i * FD + t] + part[t] + part[t + FD] + bpl[t];
        g_hf[i * FD + t] = nhf;
        nhfs[t] = nhf;
    }
    __syncthreads();

    if (doNext) {
        float a0 = 0.f, a1 = 0.f, b0 = 0.f, b1 = 0.f;
        const float* W1 = We0n + (1 + hh * 64) * FD;
        const float* W2 = We0n + (129 + hh * 64) * FD;
        const float* xv = nhfs + hh * 64;
#pragma unroll 4
        for (int k = 0; k < 64; k += 2) {
            a0 += xv[k] * W1[k * FD + c];       a1 += xv[k + 1] * W1[(k + 1) * FD + c];
            b0 += xv[k] * W2[k * FD + c];       b1 += xv[k + 1] * W2[(k + 1) * FD + c];
        }
        part[t] = a0 + a1;
        __syncthreads();
        if (t < FD) g_hs[i * FD + t] = part[t] + part[t + FD];
        __syncthreads();
        part[t] = b0 + b1;
        __syncthreads();
        if (t < FD) g_hr[i * FD + t] = part[t] + part[t + FD] + be0n[t];
    }
}

// -------------------- readout -----------------------------------------------
__global__ void kout(const float* __restrict__ Wv,
                     const float* __restrict__ Wr, const float* __restrict__ br,
                     float* __restrict__ out)
{
    __shared__ float red[FD];
    __shared__ float p[FD];
    int i = blockIdx.x, c = threadIdx.x;
    float hf = g_hf[i * FD + c];

    red[c] = hf;
    __syncthreads();
    for (int s = 64; s > 0; s >>= 1) {
        if (c < s) red[c] = fmaxf(red[c], red[c + s]);
        __syncthreads();
    }
    float mx = red[0];
    __syncthreads();
    float ex = __expf(hf - mx);
    red[c] = ex;
    __syncthreads();
    for (int s = 64; s > 0; s >>= 1) {
        if (c < s) red[c] += red[c + s];
        __syncthreads();
    }
    float inv = 1.f / red[0];
    __syncthreads();
    p[c] = ex * inv;
    __syncthreads();

    if (c < 32) {
        float a = br[c];
#pragma unroll 8
        for (int k = 0; k < FD; k++) a += p[k] * Wr[k * 32 + c];
        out[NN * 6 + i * 32 + c] = a;
    }
    if (c < 6) {
        int o = c / 3, cc = c % 3;
        out[i * 6 + c] = (g_vec[i * 3 + cc] - g_vec0[i * 3 + cc]) * Wv[o];
    }
}

// -------------------- host launch -------------------------------------------
extern "C" void kernel_launch(void* const* d_in, const int* in_sizes, int n_in,
                              void* d_out, int out_size)
{
    const float* x   = (const float*)d_in[0];
    const float* h   = (const float*)d_in[1];
    const int* snd   = (const int*)  d_in[2];
    const float* Wh0 = (const float*)d_in[4];
    const float* bh0 = (const float*)d_in[5];
    const float* We0 = (const float*)d_in[6];
    const float* be0 = (const float*)d_in[7];
    const float* We1 = (const float*)d_in[8];
    const float* be1 = (const float*)d_in[9];
    const float* We2 = (const float*)d_in[10];
    const float* be2 = (const float*)d_in[11];
    const float* Winf= (const float*)d_in[12];
    const float* binf= (const float*)d_in[13];
    const float* Wx0 = (const float*)d_in[14];
    const float* bx0 = (const float*)d_in[15];
    const float* Wx1 = (const float*)d_in[16];
    const float* bx1 = (const float*)d_in[17];
    const float* Wxo = (const float*)d_in[18];
    const float* bxo = (const float*)d_in[19];
    const float* Wp0 = (const float*)d_in[20];
    const float* bp0 = (const float*)d_in[21];
    const float* Wp1 = (const float*)d_in[22];
    const float* bp1 = (const float*)d_in[23];
    const float* Wpl = (const float*)d_in[24];
    const float* bpl = (const float*)d_in[25];
    const float* Wv  = (const float*)d_in[26];
    const float* Wr  = (const float*)d_in[27];
    const float* br  = (const float*)d_in[28];
    float* out = (float*)d_out;

    int smem = (int)sizeof(ES);
    cudaFuncSetAttribute(kedge, cudaFuncAttributeMaxDynamicSharedMemorySize, smem);

    const int WB  = FD * FD;     // 128*128 per-block weight stride
    const int W0B = 257 * FD;    // We0 per-block stride
    const int WP0 = 2 * FD * FD; // Wp0 per-block stride

    ksetup<<<1, 256>>>(x);
    knode0<<<NN, 256>>>(h, Wh0, bh0, We0, be0);
    kdummy<<<1, 32>>>();   // shifts ncu -s 5 capture onto the 2nd kedge

    for (int b = 0; b < 2; b++) {
        kedge<<<NN, 256, smem>>>(snd,
            We0 + b * W0B,
            We1 + b * WB, be1 + b * FD,
            We2 + b * WB, be2 + b * FD,
            Winf + b * FD, binf + b,
            Wx0 + b * WB, bx0 + b * FD,
            Wx1 + b * WB, bx1 + b * FD,
            Wxo + b * FD, bxo + b);
        knode<<<NN, 256>>>(Wp0 + b * WP0, bp0 + b * FD,
                           Wp1 + b * WB,  bp1 + b * FD,
                           Wpl + b * WB,  bpl + b * FD,
                           We0 + W0B, be0 + FD, b == 0 ? 1 : 0);
    }

    kout<<<NN, FD>>>(Wv, Wr, br, out);
}